// round 6
// baseline (speedup 1.0000x reference)
#include <cuda_runtime.h>
#include <cstdint>

// CIC deposition: 10M particles -> 256^3 float grid.
// Round 6: parity-split twin scratch grids. Grid py (py=0,1) stores y-pairs
// (2By+py, 2By+py+1); quad = [dy][zb] over a z-pair block Bz2. A particle
// deposits into grid py=cy&1 so its y-pair is ALWAYS within one 16B quad;
// z uses in-quad pairing (cz even: 1 quad, cz odd: 2 quads). Active REDs per
// particle = 2(x) * 1(y) * 1.5(z) = 3 (vs 5 before). Boundary corners write
// into allocated-but-never-merged slots -> no boundary predicates.
// Merge kernel: out[x][y][z] = sum_py g[py][x][By(y,py)][z>>1][dy(y,py)][z&1].

static constexpr float GMINF = -10.0f;
static constexpr float DXF   = (float)(20.0 / 255.0);

// scratch dims: x in [0,256] (257 rows; row 256 = cropped spill), By in [0,128),
// Bz2 in [0,129) (block 128 = cropped z=256 spill), quad = 4 floats (dy,zb)
static constexpr int    XDIM     = 257;
static constexpr int    BYDIM    = 128;
static constexpr int    BZDIM    = 129;
static constexpr size_t XSTRIDE  = (size_t)BYDIM * BZDIM * 4;     // 66048 floats
static constexpr size_t PER_GRID = (size_t)XDIM * XSTRIDE;        // 16,974,336 floats
static constexpr size_t TOTAL_SCRATCH = 2 * PER_GRID;             // ~129.5 MB

__device__ __align__(16) float g_scratch[TOTAL_SCRATCH];

__global__ void zero_scratch_kernel(int n4) {
    int i = blockIdx.x * blockDim.x + threadIdx.x;
    if (i < n4) ((float4*)g_scratch)[i] = make_float4(0.f, 0.f, 0.f, 0.f);
}

__device__ __forceinline__ void red_v4(float* p, float a, float b, float c, float d) {
    asm volatile("red.global.add.v4.f32 [%0], {%1, %2, %3, %4};"
                 :: "l"(p), "f"(a), "f"(b), "f"(c), "f"(d) : "memory");
}

__device__ __forceinline__ void red_v4p(float* p, float a, float b, float c, float d, int pred) {
    asm volatile(
        "{\n\t"
        ".reg .pred q;\n\t"
        "setp.ne.s32 q, %5, 0;\n\t"
        "@q red.global.add.v4.f32 [%0], {%1, %2, %3, %4};\n\t"
        "}"
        :: "l"(p), "f"(a), "f"(b), "f"(c), "f"(d), "r"(pred) : "memory");
}

__device__ __forceinline__ void deposit_one(float px, float py_, float pz, float w)
{
    // Match JAX float32 arithmetic: subtract then IEEE divide
    float fx = (px  - GMINF) / DXF;
    float fy = (py_ - GMINF) / DXF;
    float fz = (pz  - GMINF) / DXF;

    float ixf = floorf(fx), iyf = floorf(fy), izf = floorf(fz);
    int cx = (int)ixf, cy = (int)iyf, cz = (int)izf;

    if ((unsigned)cx > 255u || (unsigned)cy > 255u || (unsigned)cz > 255u) return;

    float ox = fx - ixf, oy = fy - iyf, oz = fz - izf;

    // corner weight = ((w * X) * Y) * Z (reference association)
    float wx0 = w * (1.0f - ox);
    float wx1 = w * ox;
    float wy0 = 1.0f - oy, wy1 = oy;
    float wz0 = 1.0f - oz, wz1 = oz;

    int py  = cy & 1;
    int By  = cy >> 1;
    int Bz  = cz >> 1;
    int odd = cz & 1;

    // quad A (Bz): lane (dy, zb): zb0 -> z=2Bz (=cz if even, else dead->0)
    //                             zb1 -> z=2Bz+1 (=cz+1 if even, =cz if odd)
    float zA0 = odd ? 0.0f : wz0;
    float zA1 = odd ? wz0  : wz1;
    // quad B (Bz+1, only if odd): zb0 -> z=cz+1

    float* base = g_scratch + (size_t)py * PER_GRID
                + ((((size_t)cx * BYDIM + (size_t)By) * BZDIM + (size_t)Bz) << 2);

    float Y0 = wx0 * wy0, Y1 = wx0 * wy1;
    red_v4 (base,     Y0 * zA0, Y0 * zA1, Y1 * zA0, Y1 * zA1);
    red_v4p(base + 4, Y0 * wz1, 0.0f,     Y1 * wz1, 0.0f,     odd);

    float Y0b = wx1 * wy0, Y1b = wx1 * wy1;
    float* b2 = base + XSTRIDE;   // x+1 row (row 256 exists; cropped by merge)
    red_v4 (b2,     Y0b * zA0, Y0b * zA1, Y1b * zA0, Y1b * zA1);
    red_v4p(b2 + 4, Y0b * wz1, 0.0f,      Y1b * wz1, 0.0f,     odd);
}

__global__ void __launch_bounds__(256) cic_deposit_kernel(
    const float* __restrict__ pos,
    const float* __restrict__ wgt,
    int n)
{
    int t = blockIdx.x * blockDim.x + threadIdx.x;
    int base = 4 * t;
    if (base >= n) return;

    if (base + 3 < n) {
        const float4* p4 = (const float4*)pos + 3 * (size_t)t;
        float4 A = __ldcs(p4 + 0);
        float4 B = __ldcs(p4 + 1);
        float4 C = __ldcs(p4 + 2);
        float4 W = __ldcs((const float4*)wgt + t);

        deposit_one(A.x, A.y, A.z, W.x);
        deposit_one(A.w, B.x, B.y, W.y);
        deposit_one(B.z, B.w, C.x, W.z);
        deposit_one(C.y, C.z, C.w, W.w);
    } else {
        for (int i = base; i < n; i++) {
            float ppx = __ldcs(pos + 3 * (size_t)i + 0);
            float ppy = __ldcs(pos + 3 * (size_t)i + 1);
            float ppz = __ldcs(pos + 3 * (size_t)i + 2);
            float ww  = __ldcs(wgt + i);
            deposit_one(ppx, ppy, ppz, ww);
        }
    }
}

// merge: out[x][y][z], one thread produces 4 consecutive z as float4
__global__ void __launch_bounds__(256) merge_kernel(float4* __restrict__ out, int n4) {
    int t = blockIdx.x * blockDim.x + threadIdx.x;
    if (t >= n4) return;
    int z4 = t & 63;            // z block-of-4: z = 4*z4 .. 4*z4+3
    int y  = (t >> 6) & 255;
    int x  = t >> 14;

    float4 acc = make_float4(0.f, 0.f, 0.f, 0.f);

    #pragma unroll
    for (int py = 0; py < 2; py++) {
        int dy = (y & 1) ^ py;
        int By = (y - py - dy) >> 1;         // negative only for y==0, py==1
        if (By >= 0) {
            const float* b = g_scratch + (size_t)py * PER_GRID
                + (((size_t)x * BYDIM + (size_t)By) * BZDIM + (size_t)(2 * z4)) * 4
                + (size_t)(dy * 2);
            float2 a0 = *(const float2*)b;          // Bz2=2*z4:   z=4z4, 4z4+1
            float2 a1 = *(const float2*)(b + 4);    // Bz2=2*z4+1: z=4z4+2, 4z4+3
            acc.x += a0.x; acc.y += a0.y; acc.z += a1.x; acc.w += a1.y;
        }
    }
    out[t] = acc;
}

extern "C" void kernel_launch(void* const* d_in, const int* in_sizes, int n_in,
                              void* d_out, int out_size) {
    const float* positions = (const float*)d_in[0];
    const float* weights   = (const float*)d_in[1];
    float* grid = (float*)d_out;

    int n_particles = in_sizes[1];  // weights element count = N

    // 1) zero scratch
    int nz4 = (int)(TOTAL_SCRATCH / 4);
    zero_scratch_kernel<<<(nz4 + 255) / 256, 256>>>(nz4);

    // 2) deposit
    int n_threads_total = (n_particles + 3) / 4;
    int threads = 256;
    int blocks = (n_threads_total + threads - 1) / threads;
    cic_deposit_kernel<<<blocks, threads>>>(positions, weights, n_particles);

    // 3) merge parity grids into output (fully overwrites d_out)
    int n4 = out_size / 4;
    merge_kernel<<<(n4 + 255) / 256, 256>>>((float4*)grid, n4);
}

// round 7
// speedup vs baseline: 1.7148x; 1.7148x over previous
#include <cuda_runtime.h>
#include <cstdint>

// CIC deposition: 10M particles -> 256^3 float grid.
// Round 7: parity-adaptive y-pairing with TWO sequential deposit passes so the
// hot atomic footprint stays at 64MB (L2-resident). Grid A pairs y=(2By,2By+1)
// for even-cy particles; grid B pairs y=(2By+1,2By+2) for odd-cy particles.
// Quad lane = [ybit][zbit] over z-block Bz=cz>>1. Active REDs/particle = 3
// (2 x-rows x [1 quad + 0.5 quad for odd cz]). Cropped corners (x=256, z=256,
// y=256) are predicated off / never merged. Merge: out = A(y) + B(y>=1).

static constexpr float GMINF = -10.0f;
static constexpr float DXF   = (float)(20.0 / 255.0);

static constexpr size_t XSTRIDE = 128u * 128u * 4u;          // 65536 floats per x
static constexpr size_t GRIDF   = 256u * XSTRIDE;            // 16,777,216 floats = 64MB
__device__ __align__(16) float g_scratch[2 * GRIDF];         // A then B

__global__ void zero_scratch_kernel(int n4) {
    int i = blockIdx.x * blockDim.x + threadIdx.x;
    if (i < n4) ((float4*)g_scratch)[i] = make_float4(0.f, 0.f, 0.f, 0.f);
}

__device__ __forceinline__ void red_v4p(float* p, float a, float b, float c, float d, int pred) {
    asm volatile(
        "{\n\t"
        ".reg .pred q;\n\t"
        "setp.ne.s32 q, %5, 0;\n\t"
        "@q red.global.add.v4.f32 [%0], {%1, %2, %3, %4};\n\t"
        "}"
        :: "l"(p), "f"(a), "f"(b), "f"(c), "f"(d), "r"(pred) : "memory");
}

__device__ __forceinline__ void deposit_one(
    float px, float py_, float pz, float w, float* __restrict__ G, int pass)
{
    // Match JAX float32 arithmetic: subtract then IEEE divide
    float fx = (px  - GMINF) / DXF;
    float fy = (py_ - GMINF) / DXF;
    float fz = (pz  - GMINF) / DXF;

    float ixf = floorf(fx), iyf = floorf(fy), izf = floorf(fz);
    int cx = (int)ixf, cy = (int)iyf, cz = (int)izf;

    int valid = ((unsigned)cx <= 255u) & ((unsigned)cy <= 255u) & ((unsigned)cz <= 255u);
    int act   = valid & ((cy & 1) == pass);

    float ox = fx - ixf, oy = fy - iyf, oz = fz - izf;

    // corner weight = ((w * X) * Y) * Z (reference association)
    float wx0 = w * (1.0f - ox);
    float wx1 = w * ox;
    float wy0 = 1.0f - oy, wy1 = oy;
    float wz0 = 1.0f - oz, wz1 = oz;

    int By  = (cy >> 1) & 127;
    int Bz  = (cz >> 1) & 127;
    int odd = cz & 1;

    // quad at Bz, lanes [ybit*2 + zbit]; corner cy -> ybit0, cy+1 -> ybit1
    // (holds for BOTH pairings: A: (2By,2By+1), B: (2By+1,2By+2))
    float zA0 = odd ? 0.0f : wz0;    // lane z = 2Bz
    float zA1 = odd ? wz0  : wz1;    // lane z = 2Bz+1
    float t0 = wy0 * zA0, t1 = wy0 * zA1, t2 = wy1 * zA0, t3 = wy1 * zA1;
    // spill quad at Bz+1 (odd cz only): lane zbit0 = z = cz+1
    float u0 = wy0 * wz1, u2 = wy1 * wz1;

    int pz2  = act & odd & (cz < 255);   // z=256 corner cropped
    int px1  = act & (cx < 255);         // x=256 row cropped
    int pz2x = px1 & odd & (cz < 255);

    float* b0 = G + ((((size_t)(cx & 255) * 128 + (size_t)By) * 128 + (size_t)Bz) << 2);
    red_v4p(b0,     wx0 * t0, wx0 * t1, wx0 * t2, wx0 * t3, act);
    red_v4p(b0 + 4, wx0 * u0, 0.0f,     wx0 * u2, 0.0f,     pz2);

    float* b1 = b0 + XSTRIDE;
    red_v4p(b1,     wx1 * t0, wx1 * t1, wx1 * t2, wx1 * t3, px1);
    red_v4p(b1 + 4, wx1 * u0, 0.0f,     wx1 * u2, 0.0f,     pz2x);
}

__global__ void __launch_bounds__(256) cic_deposit_kernel(
    const float* __restrict__ pos,
    const float* __restrict__ wgt,
    int n, int pass)
{
    float* G = g_scratch + (size_t)pass * GRIDF;

    int t = blockIdx.x * blockDim.x + threadIdx.x;
    int base = 4 * t;
    if (base >= n) return;

    if (base + 3 < n) {
        const float4* p4 = (const float4*)pos + 3 * (size_t)t;
        float4 A = __ldcs(p4 + 0);
        float4 B = __ldcs(p4 + 1);
        float4 C = __ldcs(p4 + 2);
        float4 W = __ldcs((const float4*)wgt + t);

        deposit_one(A.x, A.y, A.z, W.x, G, pass);
        deposit_one(A.w, B.x, B.y, W.y, G, pass);
        deposit_one(B.z, B.w, C.x, W.z, G, pass);
        deposit_one(C.y, C.z, C.w, W.w, G, pass);
    } else {
        for (int i = base; i < n; i++) {
            float ppx = __ldcs(pos + 3 * (size_t)i + 0);
            float ppy = __ldcs(pos + 3 * (size_t)i + 1);
            float ppz = __ldcs(pos + 3 * (size_t)i + 2);
            float ww  = __ldcs(wgt + i);
            deposit_one(ppx, ppy, ppz, ww, G, pass);
        }
    }
}

// merge: out[x][y][z] = A(x,y,z) + B(x,y,z); thread makes float4 of 4 z values.
// y is warp-uniform (z4 = t&63 varies within warp) -> uniform y>0 branch.
__global__ void __launch_bounds__(256) merge_kernel(float4* __restrict__ out, int n4) {
    int t = blockIdx.x * blockDim.x + threadIdx.x;
    if (t >= n4) return;
    int z4 = t & 63;             // z = 4*z4 .. 4*z4+3, Bz = 2*z4, 2*z4+1
    int y  = (t >> 6) & 255;
    int x  = t >> 14;

    // grid A: By = y>>1, ybit = y&1
    const float* a = g_scratch
        + ((((size_t)x * 128 + (size_t)(y >> 1)) * 128 + (size_t)(z4 << 1)) << 2)
        + (size_t)((y & 1) << 1);
    float2 a0 = *(const float2*)a;
    float2 a1 = *(const float2*)(a + 4);
    float4 r = make_float4(a0.x, a0.y, a1.x, a1.y);

    if (y > 0) {
        // grid B: y = 2By+1+ybit -> By = (y-1)>>1, ybit = (y-1)&1
        int yb = y - 1;
        const float* b = g_scratch + GRIDF
            + ((((size_t)x * 128 + (size_t)(yb >> 1)) * 128 + (size_t)(z4 << 1)) << 2)
            + (size_t)((yb & 1) << 1);
        float2 b0 = *(const float2*)b;
        float2 b1 = *(const float2*)(b + 4);
        r.x += b0.x; r.y += b0.y; r.z += b1.x; r.w += b1.y;
    }
    out[t] = r;
}

extern "C" void kernel_launch(void* const* d_in, const int* in_sizes, int n_in,
                              void* d_out, int out_size) {
    const float* positions = (const float*)d_in[0];
    const float* weights   = (const float*)d_in[1];
    float* grid = (float*)d_out;

    int n_particles = in_sizes[1];  // weights element count = N

    // 1) zero both scratch grids (128MB)
    int nz4 = (int)(2 * GRIDF / 4);
    zero_scratch_kernel<<<(nz4 + 255) / 256, 256>>>(nz4);

    // 2) two deposit passes: pass p handles particles with (cy&1)==p,
    //    keeping one 64MB grid hot (L2-resident) at a time
    int n_threads_total = (n_particles + 3) / 4;
    int threads = 256;
    int blocks = (n_threads_total + threads - 1) / threads;
    cic_deposit_kernel<<<blocks, threads>>>(positions, weights, n_particles, 0);
    cic_deposit_kernel<<<blocks, threads>>>(positions, weights, n_particles, 1);

    // 3) merge parity grids into output (fully overwrites d_out)
    int n4 = out_size / 4;
    merge_kernel<<<(n4 + 255) / 256, 256>>>((float4*)grid, n4);
}